// round 9
// baseline (speedup 1.0000x reference)
#include <cuda_runtime.h>
#include <cooperative_groups.h>
#include <math.h>

namespace cg = cooperative_groups;

#define N_IMG   64
#define C_PRED  85
#define HDIM    32
#define HW      1024
#define NCLS    80
#define CONF_TH 0.25f
#define NMS_TH  0.35f
#define MAXK    64
#define CLUSTER 8
#define CPC     128          // cells per CTA
#define LCLS    10           // classes hosted per CTA (class c lives in rank c%8, local idx c/8)

// Output layout (float32): [ bboxes: N*HW*6 ][ keep: N*HW ]
#define BBOX_ELEMS ((size_t)N_IMG * HW * 6)

__global__ __launch_bounds__(128) __cluster_dims__(CLUSTER, 1, 1)
void fastestdet_cluster_kernel(const float* __restrict__ preds,
                               float* __restrict__ out)
{
    __shared__ float4             sbox[CPC];              // my 128 cells' boxes
    __shared__ unsigned long long ckey[LCLS * MAXK];      // buckets for my 10 classes
    __shared__ int                ccnt[LCLS];
    __shared__ unsigned char      skeep[CPC];
    __shared__ unsigned long long srtkey[4 * 32];         // per-warp staging
    __shared__ float4             srtbox[4 * 32];
    __shared__ unsigned           Msm   [4 * 32];

    cg::cluster_group cluster = cg::this_cluster();
    const int rank = blockIdx.x;                 // 0..7 within cluster
    const int n    = blockIdx.y;                 // image
    const int tid  = threadIdx.x;                // 0..127
    const int t    = rank * CPC + tid;           // global cell 0..1023

    if (tid < LCLS) ccnt[tid] = 0;
    skeep[tid] = 0;

    // ---------------- Phase 1: decode (full chip: 512 CTAs) ----------------
    const float* p = preds + (size_t)n * C_PRED * HW + t;

    const float pobj = p[0];
    const float r0 = p[1 * HW];
    const float r1 = p[2 * HW];
    const float r2 = p[3 * HW];
    const float r3 = p[4 * HW];

    float mx = p[5 * HW];
    int   am = 0;
    #pragma unroll 8
    for (int c = 1; c < NCLS; ++c) {
        float v = p[(5 + c) * HW];
        if (v > mx) { mx = v; am = c; }   // strict '>' => first max index (jnp.argmax)
    }
    const float score = pobj * mx;

    const int gw = t & (HDIM - 1);
    const int gh = t >> 5;

    const float bw  = 1.0f / (1.0f + expf(-r2));
    const float bh  = 1.0f / (1.0f + expf(-r3));
    const float bcx = (tanhf(r0) + (float)gw) * (1.0f / 32.0f);  // /32 exact
    const float bcy = (tanhf(r1) + (float)gh) * (1.0f / 32.0f);

    const float x1 = bcx - 0.5f * bw;
    const float y1 = bcy - 0.5f * bh;
    const float x2 = bcx + 0.5f * bw;
    const float y2 = bcy + 0.5f * bh;

    float* ob = out + ((size_t)n * HW + t) * 6;
    ob[0] = x1; ob[1] = y1; ob[2] = x2; ob[3] = y2;
    ob[4] = score; ob[5] = (float)am;

    sbox[tid] = make_float4(x1, y1, x2, y2);

    cluster.sync();   // all ccnt initialized, all sbox written

    // ---------------- Phase 2: bucket by class into owner CTA (DSMEM) ----------------
    if (score > CONF_TH) {
        const int dst = am & 7;           // owner rank
        const int lc  = am >> 3;          // local class index there
        int* pc = cluster.map_shared_rank(&ccnt[lc], dst);
        const int slot = atomicAdd(pc, 1);
        if (slot < MAXK) {
            unsigned long long* pk =
                cluster.map_shared_rank(&ckey[lc * MAXK + slot], dst);
            *pk = (((unsigned long long)__float_as_uint(score)) << 10)
                  | (unsigned long long)(HW - 1 - t);
        }
    }
    cluster.sync();   // buckets complete

    // ---------------- Phase 3: matrix greedy NMS on local classes ----------------
    const int wp   = tid >> 5;
    const int lane = tid & 31;

    for (int lc = wp; lc < LCLS; lc += 4) {
        int k = ccnt[lc];
        if (k > MAXK) k = MAXK;
        if (k == 0) continue;

        if (k <= 32) {
            // load my key (local LDS) + my box (DSMEM gather, per-lane parallel)
            unsigned long long key = 0;
            float4 cb = make_float4(0.f, 0.f, 0.f, 0.f);
            if (lane < k) {
                key = ckey[lc * MAXK + lane];
                const int bi = (HW - 1) - (int)(key & (HW - 1));
                cb = *cluster.map_shared_rank(&sbox[bi & (CPC - 1)], bi >> 7);
            }

            // rank = #{keys strictly greater} (stable argsort(-score); keys distinct)
            int rnk = 0;
            for (int j = 0; j < k; ++j) {
                const unsigned long long kj = ckey[lc * MAXK + j];  // broadcast LDS
                if (lane < k && kj > key) ++rnk;
            }

            // permute to lane == rank
            if (lane < k) {
                srtkey[wp * 32 + rnk] = key;
                srtbox[wp * 32 + rnk] = cb;
            }
            __syncwarp();

            int    sbi = 0;
            float4 scb = make_float4(0.f, 0.f, 0.f, 0.f);
            float  area = 0.f;
            if (lane < k) {
                scb  = srtbox[wp * 32 + lane];
                sbi  = (HW - 1) - (int)(srtkey[wp * 32 + lane] & (HW - 1));
                area = (scb.z - scb.x) * (scb.w - scb.y);
            }

            // suppression row (IoU symmetric)
            unsigned M = 0;
            if (lane < k) {
                for (int j = 0; j < k; ++j) {
                    const float4 kb = srtbox[wp * 32 + j];          // broadcast LDS128
                    float iw = fminf(scb.z, kb.z) - fmaxf(scb.x, kb.x);
                    iw = fmaxf(iw, 0.0f);
                    float ih = fminf(scb.w, kb.w) - fmaxf(scb.y, kb.y);
                    ih = fmaxf(ih, 0.0f);
                    const float inter = iw * ih;
                    const float kba = (kb.z - kb.x) * (kb.w - kb.y);
                    const float iou = inter / (area + kba - inter + 1e-9f);
                    if (iou > NMS_TH) M |= (1u << j);
                }
                Msm[wp * 32 + lane] = M;
            }
            __syncwarp();

            // uniform scalar greedy (self-bit harmless: cleared first)
            unsigned alive = (k == 32) ? 0xffffffffu : ((1u << k) - 1u);
            unsigned kept = 0;
            while (alive) {
                const int pb = __ffs(alive) - 1;
                kept  |= (1u << pb);
                alive &= ~(1u << pb);
                alive &= ~Msm[wp * 32 + pb];                        // broadcast LDS
            }
            if (lane < k && ((kept >> lane) & 1u)) {
                unsigned char* pk =
                    cluster.map_shared_rank(&skeep[sbi & (CPC - 1)], sbi >> 7);
                *pk = 1;
            }
            __syncwarp();   // srt buffers reused next class
        } else if (lane == 0) {
            // rare fallback: serial greedy (32 < k <= 64)
            const unsigned long long* keys = &ckey[lc * MAXK];
            unsigned long long alive = (k >= 64) ? ~0ull : ((1ull << k) - 1ull);
            while (alive) {
                unsigned long long best = 0; int bs = 0;
                unsigned long long m = alive;
                while (m) {
                    const int j = __ffsll((long long)m) - 1;
                    m &= m - 1;
                    if (keys[j] > best) { best = keys[j]; bs = j; }
                }
                const int bib = (HW - 1) - (int)(best & (HW - 1));
                unsigned char* pkk =
                    cluster.map_shared_rank(&skeep[bib & (CPC - 1)], bib >> 7);
                *pkk = 1;
                alive &= ~(1ull << bs);

                const float4 cbb =
                    *cluster.map_shared_rank(&sbox[bib & (CPC - 1)], bib >> 7);
                const float ca = (cbb.z - cbb.x) * (cbb.w - cbb.y);
                m = alive;
                while (m) {
                    const int j = __ffsll((long long)m) - 1;
                    m &= m - 1;
                    const int bj = (HW - 1) - (int)(keys[j] & (HW - 1));
                    const float4 kb =
                        *cluster.map_shared_rank(&sbox[bj & (CPC - 1)], bj >> 7);
                    float iw = fminf(cbb.z, kb.z) - fmaxf(cbb.x, kb.x);
                    iw = fmaxf(iw, 0.0f);
                    float ih = fminf(cbb.w, kb.w) - fmaxf(cbb.y, kb.y);
                    ih = fmaxf(ih, 0.0f);
                    const float inter = iw * ih;
                    const float kba = (kb.z - kb.x) * (kb.w - kb.y);
                    const float iou = inter / (ca + kba - inter + 1e-9f);
                    if (iou > NMS_TH) alive &= ~(1ull << j);
                }
            }
        }
    }

    cluster.sync();   // all skeep writes visible to owners

    // ---------------- Phase 4: coalesced keep writeout ----------------
    out[BBOX_ELEMS + (size_t)n * HW + t] = (float)skeep[tid];
}

extern "C" void kernel_launch(void* const* d_in, const int* in_sizes, int n_in,
                              void* d_out, int out_size)
{
    (void)in_sizes; (void)n_in; (void)out_size;
    const float* preds = (const float*)d_in[0];
    float* out = (float*)d_out;
    fastestdet_cluster_kernel<<<dim3(CLUSTER, N_IMG), CPC>>>(preds, out);
}